// round 17
// baseline (speedup 1.0000x reference)
#include <cuda_runtime.h>
#include <cstdint>

#define C_EPS     1e-12f
#define C_TOL     1e-6f
#define C_LAM     10000.0f
#define C_INVLAM  1e-4f

typedef unsigned long long u64;

// ---- packed f32x2 helpers (sm_103a) ----
__device__ __forceinline__ u64 pk2(float lo, float hi) {
    u64 r; asm("mov.b64 %0, {%1, %2};" : "=l"(r) : "f"(lo), "f"(hi)); return r;
}
__device__ __forceinline__ void upk2(float& lo, float& hi, u64 v) {
    asm("mov.b64 {%0, %1}, %2;" : "=f"(lo), "=f"(hi) : "l"(v));
}
__device__ __forceinline__ u64 f2fma(u64 a, u64 b, u64 c) {
    u64 r; asm("fma.rn.f32x2 %0, %1, %2, %3;" : "=l"(r) : "l"(a), "l"(b), "l"(c)); return r;
}
__device__ __forceinline__ u64 f2mul(u64 a, u64 b) {
    u64 r; asm("mul.rn.f32x2 %0, %1, %2;" : "=l"(r) : "l"(a), "l"(b)); return r;
}
__device__ __forceinline__ float frcp(float x) {
    float r; asm("rcp.approx.f32 %0, %1;" : "=f"(r) : "f"(x)); return r;
}

// Per-row state. a_cbf = -2*p_rel is never formed: A = 4|p|^2, u - t*a = u + 2t*p.
struct Row {
    float A, p, N, b;
    float t, lb, hb;
    float s1, t2;
    float ux, uy, px, py;
    bool f1, o2;
};

// Scalar prologue: cases 1/2 predicates, case-3 start + safeguard bounds.
// Numerics identical to passing R16 (modulo exact-2x scalings, ulp-equivalent).
__device__ __forceinline__ Row prep(float ux, float uy, float px, float py,
                                    float vx, float vy) {
    Row r;
    r.ux = ux; r.uy = uy; r.px = px; r.py = py;
    float d  = fmaf(px, px, py * py);                    // |p_rel|^2
    float pv = fmaf(px, vx, py * vy);
    float b  = fmaf(2.0f, d, fmaf(-2.0f, pv, -2.0f));    // 2(d-1) - 2 p.v
    float A  = 4.0f * d;
    float p  = -2.0f * fmaf(px, ux, py * uy);
    float N  = fmaf(ux, ux, uy * uy);
    r.A = A; r.p = p; r.N = N; r.b = b;

    // Case 1 (feasibility via p*s1 — validated in R16)
    float s1 = fminf(1.0f, rsqrtf(fmaxf(N, C_EPS)));
    r.s1 = s1;
    r.f1 = p * s1 <= b + C_TOL;

    // Case 2 (formed-vector ball test — mandatory, R9/R10 lesson)
    float t2 = __fdividef(C_LAM * (p - b), fmaf(C_LAM, A, 1.0f));
    r.t2 = t2;
    float u2x = fmaf(2.0f * t2, px, ux), u2y = fmaf(2.0f * t2, py, uy);
    r.o2 = (t2 >= -C_TOL) && (fmaf(u2x, u2x, u2y * u2y) <= 1.0f + C_TOL);

    // Case 3 start: quadratic (s>0) / cubic-balance (s<=0)
    float Ac   = fmaxf(A, 1e-30f);
    float rsA  = rsqrtf(Ac);
    float m    = Ac * rsA;                 // sqrt(A)
    float invA = rsA * rsA;                // 1/A
    float s    = fmaf(-b, b, A);           // A - b^2
    float cs   = fmaxf(fmaf(A, N, -p * p), 1e-30f);
    float q    = cs * invA;
    float rad  = cs * rsqrtf(cs) * rsqrtf(s);            // nan if s<=0 (not selected)
    float t_q  = fmaf(-b, rad, p) * invA;
    float a_x  = fmaxf(p * invA, 0.0f) + C_LAM * fmaxf(-b - m, 0.0f);
    float c_c  = fmaxf((0.5f * C_LAM) * ((-b) * q) * invA, 0.0f);
    float cr   = exp2f(0.33333333f * __log2f(c_c));      // cbrt; 0 if c_c=0
    float den  = a_x + cr;
    float t_x  = a_x + __fdividef(c_c, fmaxf(den * den, 1e-30f));
    float t3   = (s > 0.0f) ? t_q : t_x;

    float poA = p * invA;
    float hb = poA, lb = 0.0f;
    if (b < 0.0f) {
        hb = fmaxf(hb, -C_LAM * b);
        if (fmaf(poA, C_INVLAM, b) < 0.0f) lb = poA;     // excludes spurious F-root
    }
    r.lb = lb; r.hb = hb;
    r.t = fminf(fmaxf(t3, lb), hb);
    return r;
}

// Packed Newton on F(t) = L^2 - R^2*nrm2 for two rows at once.
// Scalar escapes: rcp (MUFU) and per-lane clamp (also inf/nan recovery).
__device__ __forceinline__ void newton_pair(Row& r0, Row& r1) {
    u64 A2  = pk2(r0.A, r1.A);
    u64 nA2 = pk2(-r0.A, -r1.A);
    u64 P2  = pk2(r0.p, r1.p);
    u64 mp2 = pk2(-2.0f * r0.p, -2.0f * r1.p);
    u64 N2  = pk2(r0.N, r1.N);
    u64 B2  = pk2(r0.b, r1.b);
    u64 nB2 = pk2(-r0.b, -r1.b);
    u64 T   = pk2(r0.t, r1.t);
    const u64 IL  = pk2(C_INVLAM, C_INVLAM);
    const u64 NIL = pk2(-C_INVLAM, -C_INVLAM);
    const u64 NH  = pk2(-0.5f, -0.5f);

    #pragma unroll
    for (int k = 0; k < 4; k++) {
        u64 nr2 = f2fma(T, f2fma(T, A2, mp2), N2);       // ||u - t a||^2
        u64 L   = f2fma(T, nA2, P2);                     // p - tA
        u64 R   = f2fma(T, IL, B2);                      // b + t/LAM
        u64 Rg  = f2fma(T, NIL, nB2);                    // -(b + t/LAM)
        u64 Rr  = f2mul(R, nr2);                         // R*nrm2
        u64 F   = f2fma(L, L, f2mul(Rg, Rr));            // L^2 - R^2*nrm2
        u64 s2  = f2fma(R, R, nA2);                      // R^2 - A
        u64 Fh  = f2fma(L, s2, f2mul(NIL, Rr));          // F'/2
        u64 nhF = f2mul(F, NH);                          // -F/2
        float fa, fb; upk2(fa, fb, Fh);
        u64 rF = pk2(frcp(fa), frcp(fb));
        T = f2fma(nhF, rF, T);                           // t -= (F/2)/(F'/2)
        float ta, tb; upk2(ta, tb, T);
        ta = fminf(fmaxf(ta, r0.lb), r0.hb);             // clamp + nan recovery
        tb = fminf(fmaxf(tb, r1.lb), r1.hb);
        T = pk2(ta, tb);
    }
    float ta, tb; upk2(ta, tb, T);
    r0.t = ta; r1.t = tb;
}

__device__ __forceinline__ float2 finish(const Row& r) {
    float t3   = r.t;
    float nrm2 = fmaxf(fmaf(t3, fmaf(t3, r.A, -2.0f * r.p), r.N), C_EPS);
    float inv3 = fminf(rsqrtf(nrm2), 1.0f);
    float u3x  = fmaf(2.0f * t3, r.px, r.ux) * inv3;
    float u3y  = fmaf(2.0f * t3, r.py, r.uy) * inv3;
    float u1x  = r.ux * r.s1, u1y = r.uy * r.s1;
    float u2x  = fmaf(2.0f * r.t2, r.px, r.ux);
    float u2y  = fmaf(2.0f * r.t2, r.py, r.uy);
    float ox = r.f1 ? u1x : (r.o2 ? u2x : u3x);
    float oy = r.f1 ? u1y : (r.o2 ? u2y : u3y);
    return make_float2(ox, oy);
}

// 4 rows/thread: streaming 128b loads, two packed Newton pairs, streaming stores.
__global__ void __launch_bounds__(256, 4) cbf_fused4_kernel(
    const float4* __restrict__ u4,
    const float4* __restrict__ o4,
    float4*       __restrict__ out4,
    int nquad)
{
    int j = blockIdx.x * 256 + threadIdx.x;
    if (j >= nquad) return;

    float4 ua = __ldcs(u4 + 2 * j), ub = __ldcs(u4 + 2 * j + 1);
    float4 c0 = __ldcs(o4 + 6 * j),     c1 = __ldcs(o4 + 6 * j + 1);
    float4 c2 = __ldcs(o4 + 6 * j + 2), c3 = __ldcs(o4 + 6 * j + 3);
    float4 c4 = __ldcs(o4 + 6 * j + 4), c5 = __ldcs(o4 + 6 * j + 5);

    Row r0 = prep(ua.x, ua.y, c0.z, c0.w, c1.x, c1.y);
    Row r1 = prep(ua.z, ua.w, c2.x, c2.y, c2.z, c2.w);
    newton_pair(r0, r1);
    float2 o0 = finish(r0), o1 = finish(r1);
    __stcs(out4 + 2 * j, make_float4(o0.x, o0.y, o1.x, o1.y));

    Row r2 = prep(ub.x, ub.y, c3.z, c3.w, c4.x, c4.y);
    Row r3 = prep(ub.z, ub.w, c5.x, c5.y, c5.z, c5.w);
    newton_pair(r2, r3);
    float2 o2 = finish(r2), o3 = finish(r3);
    __stcs(out4 + 2 * j + 1, make_float4(o2.x, o2.y, o3.x, o3.y));
}

// Scalar Newton for the tail (n % 4 rows; not hit at B = 4M).
__device__ __forceinline__ float newton1(const Row& r) {
    float t3 = r.t;
    #pragma unroll
    for (int k = 0; k < 4; k++) {
        float nrm2 = fmaf(t3, fmaf(t3, r.A, -2.0f * r.p), r.N);
        float L    = fmaf(-t3, r.A, r.p);
        float R    = fmaf(t3, C_INVLAM, r.b);
        float Rn   = R * nrm2;
        float s2   = fmaf(R, R, -r.A);
        float F    = fmaf(L, L, -R * Rn);
        float Fh   = fmaf(L, s2, -C_INVLAM * Rn);
        t3 = t3 - __fdividef(0.5f * F, Fh);
        t3 = fminf(fmaxf(t3, r.lb), r.hb);
    }
    return t3;
}

__global__ void cbf_tail_kernel(
    const float* __restrict__ u_nom,
    const float* __restrict__ obs,
    float*       __restrict__ out,
    int start, int n)
{
    int i = start + threadIdx.x;
    if (i >= n) return;
    const float* o = obs + 6 * i;
    Row r = prep(u_nom[2 * i], u_nom[2 * i + 1], o[2], o[3], o[4], o[5]);
    r.t = newton1(r);
    float2 v = finish(r);
    out[2 * i]     = v.x;
    out[2 * i + 1] = v.y;
}

extern "C" void kernel_launch(void* const* d_in, const int* in_sizes, int n_in,
                              void* d_out, int out_size) {
    const float* u_nom = (const float*)d_in[0];
    const float* obs   = (const float*)d_in[1];
    float* out = (float*)d_out;

    int n = in_sizes[0] / 2;
    int nquad = n / 4;

    int threads = 256;
    int blocks  = (nquad + threads - 1) / threads;
    if (blocks > 0)
        cbf_fused4_kernel<<<blocks, threads>>>(
            (const float4*)u_nom, (const float4*)obs, (float4*)out, nquad);

    if (n & 3)
        cbf_tail_kernel<<<1, 4>>>(u_nom, obs, out, nquad * 4, n);
}